// round 4
// baseline (speedup 1.0000x reference)
#include <cuda_runtime.h>
#include <cstdint>

// Problem constants (fixed shapes in reference_code)
#define BB     1024
#define CC     20
#define NN     26
#define VDIM   128
#define NSPL   10
#define NWORDS 100000

#define GRID_BLOCKS 1216          // 8 blocks/SM x 152 SMs = one resident wave
#define TILE_F4     1024          // 256 threads x 4 float4 per block-tile (16 KB)
#define TOTAL_F4    ((size_t)NSPL * NWORDS * VDIM / 4)   // 32,000,000 (divisible by 1024)

// Fused kernel:
//   - blocks [0, BB): compute scores[b, :] for b = blockIdx.x
//   - ALL blocks: tiled, x4-unrolled streaming copy of D -> out + BB*NN
__global__ void __launch_bounds__(256, 8)
dmspline_fused(const float* __restrict__ x_vals,
               const int*   __restrict__ knot_ids,
               const int*   __restrict__ context_ids,
               const int*   __restrict__ target_ids,
               const float* __restrict__ D,
               const float* __restrict__ W,
               const float* __restrict__ O,
               float* __restrict__ out,
               int do_copy)
{
    __shared__ float sx[VDIM];
    __shared__ int   sctx[CC];

    const int bid = blockIdx.x;
    const int tid = threadIdx.x;

    if (bid < BB) {
        // ---- stage context ids through shared (one broadcast load each) ----
        if (tid < CC) sctx[tid] = context_ids[bid * CC + tid];
        __syncthreads();

        // ---- phase 1: x[v] for v = tid (threads 0..127) ----
        if (tid < VDIM) {
            const int   knot = knot_ids[bid];
            const float xv   = x_vals[bid];
            const float* __restrict__ Dk = D + (size_t)knot * NWORDS * VDIM;
            float acc = 0.0f;
            #pragma unroll
            for (int c = 0; c < CC; ++c) {
                const int ctx = sctx[c];
                const float d = __ldg(Dk + (size_t)ctx * VDIM + tid);
                const float w = __ldg(W  + (size_t)ctx * VDIM + tid);
                acc = fmaf(d, xv, acc) + w;
            }
            sx[tid] = acc * (1.0f / CC);
        }
        __syncthreads();

        // ---- phase 2: 8 warps; warp w handles n = w, w+8, ... ----
        const int warp = tid >> 5;
        const int lane = tid & 31;
        for (int n = warp; n < NN; n += 8) {
            const int id = target_ids[bid * NN + n];
            const float* __restrict__ Ocol = O + id;  // O[v*NWORDS + id]
            float s = 0.0f;
            #pragma unroll
            for (int k = 0; k < 4; ++k) {
                const int v = lane + 32 * k;
                s = fmaf(sx[v], __ldg(Ocol + (size_t)v * NWORDS), s);
            }
            #pragma unroll
            for (int off = 16; off; off >>= 1)
                s += __shfl_down_sync(0xffffffffu, s, off);
            if (lane == 0) out[bid * NN + n] = s;
        }
        // no syncthreads needed: copy below touches disjoint memory
    }

    // ---- D pass-through copy: 16 KB tiles, x4 batched loads (MLP_p1=4) ----
    if (do_copy) {
        const float4* __restrict__ src = (const float4*)D;
        float4*       __restrict__ dst = (float4*)(out + BB * NN);
        const size_t perPass = (size_t)GRID_BLOCKS * TILE_F4;
        for (size_t off = (size_t)bid * TILE_F4 + tid;
             off + (TILE_F4 - 256) < TOTAL_F4 + (size_t)tid + 1;  // off derived from tile base
             off += perPass) {
            // batch 4 independent coalesced 16B loads, then 4 stores
            float4 v0 = __ldcs(src + off);
            float4 v1 = __ldcs(src + off + 256);
            float4 v2 = __ldcs(src + off + 512);
            float4 v3 = __ldcs(src + off + 768);
            __stcs(dst + off,       v0);
            __stcs(dst + off + 256, v1);
            __stcs(dst + off + 512, v2);
            __stcs(dst + off + 768, v3);
        }
    }
}

extern "C" void kernel_launch(void* const* d_in, const int* in_sizes, int n_in,
                              void* d_out, int out_size)
{
    const float* x_vals      = (const float*)d_in[0];
    const int*   knot_ids    = (const int*)  d_in[1];
    const int*   context_ids = (const int*)  d_in[2];
    const int*   target_ids  = (const int*)  d_in[3];
    const float* D           = (const float*)d_in[4];
    const float* W           = (const float*)d_in[5];
    const float* O           = (const float*)d_in[6];
    float*       out         = (float*)d_out;

    // If the harness expects the full tuple (scores, D), out_size covers both;
    // if it only expects scores, skip the copy.
    const long long need = (long long)BB * NN + (long long)NSPL * NWORDS * VDIM;
    const int do_copy = ((long long)out_size >= need) ? 1 : 0;

    dmspline_fused<<<GRID_BLOCKS, 256>>>(x_vals, knot_ids, context_ids, target_ids,
                                         D, W, O, out, do_copy);
}

// round 5
// speedup vs baseline: 1.0364x; 1.0364x over previous
#include <cuda_runtime.h>
#include <cstdint>

// Problem constants (fixed shapes in reference_code)
#define BB     1024
#define CC     20
#define NN     26
#define VDIM   128
#define NSPL   10
#define NWORDS 100000

// Small kernel: scores only. One block per batch row.
// scores[b,n] = sum_v x[b,v] * O[v, tgt[b,n]]
// x[b,v] = (1/C) * sum_c ( D[knot[b], ctx[b,c], v] * x_vals[b] + W[ctx[b,c], v] )
__global__ void __launch_bounds__(256)
dmspline_scores(const float* __restrict__ x_vals,
                const int*   __restrict__ knot_ids,
                const int*   __restrict__ context_ids,
                const int*   __restrict__ target_ids,
                const float* __restrict__ D,
                const float* __restrict__ W,
                const float* __restrict__ O,
                float* __restrict__ out)
{
    __shared__ float sx[VDIM];
    __shared__ int   sctx[CC];

    const int bid = blockIdx.x;
    const int tid = threadIdx.x;

    // ---- stage context ids through shared ----
    if (tid < CC) sctx[tid] = context_ids[bid * CC + tid];
    __syncthreads();

    // ---- phase 1: x[v] for v = tid (threads 0..127) ----
    if (tid < VDIM) {
        const int   knot = knot_ids[bid];
        const float xv   = x_vals[bid];
        const float* __restrict__ Dk = D + (size_t)knot * NWORDS * VDIM;
        float acc = 0.0f;
        #pragma unroll
        for (int c = 0; c < CC; ++c) {
            const int ctx = sctx[c];
            const float d = __ldg(Dk + (size_t)ctx * VDIM + tid);
            const float w = __ldg(W  + (size_t)ctx * VDIM + tid);
            acc = fmaf(d, xv, acc) + w;
        }
        sx[tid] = acc * (1.0f / CC);
    }
    __syncthreads();

    // ---- phase 2: 8 warps; warp w handles n = w, w+8, ... ----
    const int warp = tid >> 5;
    const int lane = tid & 31;
    for (int n = warp; n < NN; n += 8) {
        const int id = target_ids[bid * NN + n];
        const float* __restrict__ Ocol = O + id;  // O[v*NWORDS + id]
        float s = 0.0f;
        #pragma unroll
        for (int k = 0; k < 4; ++k) {
            const int v = lane + 32 * k;
            s = fmaf(sx[v], __ldg(Ocol + (size_t)v * NWORDS), s);
        }
        #pragma unroll
        for (int off = 16; off; off >>= 1)
            s += __shfl_down_sync(0xffffffffu, s, off);
        if (lane == 0) out[bid * NN + n] = s;
    }
}

extern "C" void kernel_launch(void* const* d_in, const int* in_sizes, int n_in,
                              void* d_out, int out_size)
{
    const float* x_vals      = (const float*)d_in[0];
    const int*   knot_ids    = (const int*)  d_in[1];
    const int*   context_ids = (const int*)  d_in[2];
    const int*   target_ids  = (const int*)  d_in[3];
    const float* D           = (const float*)d_in[4];
    const float* W           = (const float*)d_in[5];
    const float* O           = (const float*)d_in[6];
    float*       out         = (float*)d_out;

    // Tiny scores kernel: 1024 blocks x 256 threads (~5 us)
    dmspline_scores<<<BB, 256>>>(x_vals, knot_ids, context_ids, target_ids,
                                 D, W, O, out);

    // D pass-through via the driver's D2D memcpy path (graph memcpy node).
    // cudaMemcpyAsync D2D is explicitly allowed and graph-capturable.
    const long long dElems = (long long)NSPL * NWORDS * VDIM;
    const long long need   = (long long)BB * NN + dElems;
    if ((long long)out_size >= need) {
        cudaMemcpyAsync(out + (size_t)BB * NN, D,
                        (size_t)dElems * sizeof(float),
                        cudaMemcpyDeviceToDevice, 0);
    }
}